// round 2
// baseline (speedup 1.0000x reference)
#include <cuda_runtime.h>
#include <cuda_bf16.h>
#include <mma.h>
#include <math.h>

using namespace nvcuda;

#define NVOC 50257
#define NIN  1024
#define NH   1024
#define H2   2048
#define G4   8192      // 4*H2
#define BB   64        // batch
#define TT   1024      // time steps
#define MROWS (TT*BB)  // 65536

// ---------------- scratch (no allocations allowed) ----------------
__device__ float g_wa[BB*NH];       // h_prev @ attWa
__device__ float g_score[TT*BB];    // (T,B) scores -> softmax weights
__device__ float g_ctx[BB*NH];      // context vector
__device__ float g_emb[BB*NIN];     // gathered embeddings
__device__ float g_gates[BB*G4];    // LSTM pre-activations

__device__ __forceinline__ float tanh_approx(float x) {
    float y; asm("tanh.approx.f32 %0, %1;" : "=f"(y) : "f"(x)); return y;
}
__device__ __forceinline__ float sigmoid_acc(float x) {
    return 1.0f / (1.0f + expf(-x));
}

// ---------------- 1: zero score + gather embeddings ----------------
__global__ void k_init_emb(const int* __restrict__ inputs,
                           const float* __restrict__ enc_w) {
    int idx = blockIdx.x * blockDim.x + threadIdx.x;  // 65536
    g_score[idx] = 0.0f;
    int b = idx >> 10, c = idx & 1023;
    g_emb[idx] = enc_w[(size_t)inputs[b] * NIN + c];
}

// ---------------- 2: wa = h_prev @ attWa  (64x1024, K=1024) ----------------
__global__ void k_wa(const float* __restrict__ h_prev,
                     const float* __restrict__ attWa) {
    int b = blockIdx.y;
    int n = blockIdx.x * 256 + threadIdx.x;
    __shared__ float hs[NH];
    for (int i = threadIdx.x; i < NH; i += 256) hs[i] = h_prev[b * NH + i];
    __syncthreads();
    float acc = 0.0f;
#pragma unroll 8
    for (int k = 0; k < NH; k++) acc += hs[k] * __ldg(attWa + (size_t)k * NH + n);
    g_wa[b * NH + n] = acc;
}

// ---------------- 3: fused attention GEMM (tf32 wmma) ----------------
// score[row] += sum_j attV[j] * tanh( (mem @ attUa)[row,j] + wa[row%64, j] )
#define BM 128
#define BN 64
#define BK 32
#define LDA 36
#define LDB 68
#define LDC 68

__global__ __launch_bounds__(256) void k_att(const float* __restrict__ mem,
                                             const float* __restrict__ attUa,
                                             const float* __restrict__ attV) {
    __shared__ float smem[BM * LDC];  // 8704 floats; reused: [As|Bs] then Cs
    float* As = smem;                  // [BM][LDA]
    float* Bs = smem + BM * LDA;       // [BK][LDB]
    float* Cs = smem;                  // [BM][LDC]

    const int row0 = blockIdx.y * BM;
    const int n0   = blockIdx.x * BN;
    const int tid  = threadIdx.x;
    const int wid  = tid >> 5;
    const int wm   = wid >> 1;   // 0..3
    const int wn   = wid & 1;    // 0..1

    wmma::fragment<wmma::accumulator, 16, 16, 8, float> acc[2][2];
#pragma unroll
    for (int i = 0; i < 2; i++)
#pragma unroll
        for (int j = 0; j < 2; j++) wmma::fill_fragment(acc[i][j], 0.0f);

    for (int k0 = 0; k0 < NH; k0 += BK) {
        // A tile: 128x32
#pragma unroll
        for (int i = 0; i < 4; i++) {
            int r = (tid >> 3) + i * 32;
            int q = tid & 7;
            float4 v = *(const float4*)(mem + (size_t)(row0 + r) * NH + k0 + q * 4);
            v.x = wmma::__float_to_tf32(v.x); v.y = wmma::__float_to_tf32(v.y);
            v.z = wmma::__float_to_tf32(v.z); v.w = wmma::__float_to_tf32(v.w);
            *(float4*)&As[r * LDA + q * 4] = v;
        }
        // B tile: 32x64
#pragma unroll
        for (int i = 0; i < 2; i++) {
            int r = (tid >> 4) + i * 16;
            int q = tid & 15;
            float4 v = *(const float4*)(attUa + (size_t)(k0 + r) * NH + n0 + q * 4);
            v.x = wmma::__float_to_tf32(v.x); v.y = wmma::__float_to_tf32(v.y);
            v.z = wmma::__float_to_tf32(v.z); v.w = wmma::__float_to_tf32(v.w);
            *(float4*)&Bs[r * LDB + q * 4] = v;
        }
        __syncthreads();
#pragma unroll
        for (int ks = 0; ks < 4; ks++) {
            wmma::fragment<wmma::matrix_a, 16, 16, 8, wmma::precision::tf32, wmma::row_major> af[2];
            wmma::fragment<wmma::matrix_b, 16, 16, 8, wmma::precision::tf32, wmma::row_major> bf[2];
#pragma unroll
            for (int i = 0; i < 2; i++)
                wmma::load_matrix_sync(af[i], &As[(wm * 32 + i * 16) * LDA + ks * 8], LDA);
#pragma unroll
            for (int j = 0; j < 2; j++)
                wmma::load_matrix_sync(bf[j], &Bs[(ks * 8) * LDB + wn * 32 + j * 16], LDB);
#pragma unroll
            for (int i = 0; i < 2; i++)
#pragma unroll
                for (int j = 0; j < 2; j++)
                    wmma::mma_sync(acc[i][j], af[i], bf[j], acc[i][j]);
        }
        __syncthreads();
    }

    // dump accumulators to smem
#pragma unroll
    for (int i = 0; i < 2; i++)
#pragma unroll
        for (int j = 0; j < 2; j++)
            wmma::store_matrix_sync(&Cs[(wm * 32 + i * 16) * LDC + wn * 32 + j * 16],
                                    acc[i][j], LDC, wmma::mem_row_major);
    __syncthreads();

    // epilogue: tanh + attV dot, reduce over j, atomic into score
    int r    = tid >> 1;
    int half = tid & 1;
    int row  = row0 + r;
    int b    = row & (BB - 1);
    const float* waRow = g_wa + b * NH + n0 + half * 32;
    const float* avp   = attV + n0 + half * 32;
    const float* crow  = &Cs[r * LDC + half * 32];
    float partial = 0.0f;
#pragma unroll
    for (int jj = 0; jj < 32; jj++)
        partial += __ldg(avp + jj) * tanh_approx(crow[jj] + __ldg(waRow + jj));
    partial += __shfl_down_sync(0xffffffffu, partial, 1);
    if (half == 0) atomicAdd(&g_score[row], partial);
}

// ---------------- 4: softmax over t (per batch column) ----------------
__global__ void k_softmax() {
    int b = blockIdx.x;
    int tid = threadIdx.x;
    __shared__ float red[256];
    float vals[4];
    float mx = -1e30f;
#pragma unroll
    for (int i = 0; i < 4; i++) {
        vals[i] = g_score[(tid + i * 256) * BB + b];
        mx = fmaxf(mx, vals[i]);
    }
    red[tid] = mx; __syncthreads();
    for (int s = 128; s > 0; s >>= 1) {
        if (tid < s) red[tid] = fmaxf(red[tid], red[tid + s]);
        __syncthreads();
    }
    mx = red[0]; __syncthreads();
    float sum = 0.0f;
#pragma unroll
    for (int i = 0; i < 4; i++) { vals[i] = expf(vals[i] - mx); sum += vals[i]; }
    red[tid] = sum; __syncthreads();
    for (int s = 128; s > 0; s >>= 1) {
        if (tid < s) red[tid] += red[tid + s];
        __syncthreads();
    }
    float inv = 1.0f / red[0];
#pragma unroll
    for (int i = 0; i < 4; i++)
        g_score[(tid + i * 256) * BB + b] = vals[i] * inv;
}

// ---------------- 5: context = sum_t w[t,b] * mem[t,b,:] ----------------
__global__ void k_ctx(const float* __restrict__ mem) {
    int b = blockIdx.y;
    int j = blockIdx.x * 256 + threadIdx.x;
    __shared__ float w[TT];
    for (int t = threadIdx.x; t < TT; t += 256) w[t] = g_score[t * BB + b];
    __syncthreads();
    float acc = 0.0f;
#pragma unroll 4
    for (int t = 0; t < TT; t++)
        acc += w[t] * mem[((size_t)t * BB + b) * NH + j];
    g_ctx[b * NH + j] = acc;
}

// ---------------- 6: gates = [emb|h_prev|ctx] @ [W_ih;W_hh]  (64x8192, K=3072) --
__global__ __launch_bounds__(256) void k_gates(const float* __restrict__ h_prev,
                                               const float* __restrict__ W_ih,
                                               const float* __restrict__ W_hh) {
    const int n0 = blockIdx.x * 64;
    __shared__ float Xs[64][20];
    __shared__ float Ws[16][68];
    float acc[4][4] = {};
    const int ty = threadIdx.x / 16, tx = threadIdx.x % 16;

    for (int k0 = 0; k0 < 3072; k0 += 16) {
        // X tile 64x16
        {
            int m = threadIdx.x >> 2, q = threadIdx.x & 3;
            int kk = k0 + q * 4;
            const float* src;
            if (k0 < 1024)       src = g_emb + m * 1024 + kk;
            else if (k0 < 2048)  src = h_prev + m * 1024 + (kk - 1024);
            else                 src = g_ctx + m * 1024 + (kk - 2048);
            *(float4*)&Xs[m][q * 4] = *(const float4*)src;
        }
        // W tile 16x64
        {
            int r = threadIdx.x / 16, q = threadIdx.x % 16;
            int krow = k0 + r;
            const float* wsrc = (krow < 1024) ? (W_ih + (size_t)krow * G4)
                                              : (W_hh + (size_t)(krow - 1024) * G4);
            *(float4*)&Ws[r][q * 4] = *(const float4*)(wsrc + n0 + q * 4);
        }
        __syncthreads();
#pragma unroll
        for (int kk = 0; kk < 16; kk++) {
            float a[4], bv[4];
#pragma unroll
            for (int i = 0; i < 4; i++) a[i] = Xs[ty * 4 + i][kk];
#pragma unroll
            for (int j = 0; j < 4; j++) bv[j] = Ws[kk][tx * 4 + j];
#pragma unroll
            for (int i = 0; i < 4; i++)
#pragma unroll
                for (int j = 0; j < 4; j++) acc[i][j] += a[i] * bv[j];
        }
        __syncthreads();
    }
#pragma unroll
    for (int i = 0; i < 4; i++)
#pragma unroll
        for (int j = 0; j < 4; j++)
            g_gates[(size_t)(ty * 4 + i) * G4 + n0 + tx * 4 + j] = acc[i][j];
}

// ---------------- 7: LSTM elementwise ----------------
__global__ void k_lstm(const float* __restrict__ c_prev,
                       const float* __restrict__ b_lstm,
                       float* __restrict__ out_ht,
                       float* __restrict__ out_ct) {
    int idx = blockIdx.x * 256 + threadIdx.x;  // 131072
    int b = idx >> 11, n = idx & 2047;
    const float* g = g_gates + (size_t)b * G4;
    float i_ = g[n]        + b_lstm[n];
    float f_ = g[n + 2048] + b_lstm[n + 2048];
    float gg = g[n + 4096] + b_lstm[n + 4096];
    float o_ = g[n + 6144] + b_lstm[n + 6144];
    float c = sigmoid_acc(f_) * c_prev[idx] + sigmoid_acc(i_) * tanhf(gg);
    out_ct[idx] = c;
    float h = sigmoid_acc(o_) * tanhf(c);
    if (n < 1024) out_ht[b * 1024 + n] = h;
}

// ---------------- 8: decoded = ht @ dec_w^T + dec_b  (64 x 50257, K=1024) -----
__global__ __launch_bounds__(256) void k_dec(const float* __restrict__ dec_w,
                                             const float* __restrict__ dec_b,
                                             const float* __restrict__ ht,
                                             float* __restrict__ out) {
    const int v0 = blockIdx.x * 128;
    __shared__ float As[128][20];  // dec_w tile 128x16
    __shared__ float Hs[16][68];   // ht^T tile 16x64
    float acc[4][8] = {};
    const int ty = threadIdx.x / 8;  // 0..31
    const int tx = threadIdx.x % 8;  // 0..7

    for (int k0 = 0; k0 < 1024; k0 += 16) {
#pragma unroll
        for (int i = 0; i < 2; i++) {
            int r = (threadIdx.x >> 2) + i * 64;
            int q = threadIdx.x & 3;
            float4 v = make_float4(0.f, 0.f, 0.f, 0.f);
            if (v0 + r < NVOC)
                v = *(const float4*)(dec_w + (size_t)(v0 + r) * 1024 + k0 + q * 4);
            *(float4*)&As[r][q * 4] = v;
        }
        {
            int b = threadIdx.x >> 2, q = threadIdx.x & 3;
            float4 v = *(const float4*)(ht + b * 1024 + k0 + q * 4);
            Hs[q * 4 + 0][b] = v.x; Hs[q * 4 + 1][b] = v.y;
            Hs[q * 4 + 2][b] = v.z; Hs[q * 4 + 3][b] = v.w;
        }
        __syncthreads();
#pragma unroll
        for (int kk = 0; kk < 16; kk++) {
            float a[4], h[8];
#pragma unroll
            for (int i = 0; i < 4; i++) a[i] = As[ty * 4 + i][kk];
#pragma unroll
            for (int j = 0; j < 8; j++) h[j] = Hs[kk][tx * 8 + j];
#pragma unroll
            for (int i = 0; i < 4; i++)
#pragma unroll
                for (int j = 0; j < 8; j++) acc[i][j] += a[i] * h[j];
        }
        __syncthreads();
    }
#pragma unroll
    for (int i = 0; i < 4; i++) {
        int v = v0 + ty * 4 + i;
        if (v < NVOC) {
            float bias = dec_b[v];
#pragma unroll
            for (int j = 0; j < 8; j++)
                out[(size_t)(tx * 8 + j) * NVOC + v] = acc[i][j] + bias;
        }
    }
}

// ---------------- launch ----------------
extern "C" void kernel_launch(void* const* d_in, const int* in_sizes, int n_in,
                              void* d_out, int out_size) {
    const int*   inputs   = (const int*)  d_in[0];
    const float* mem      = (const float*)d_in[1];
    const float* h_prev   = (const float*)d_in[2];
    const float* c_prev   = (const float*)d_in[3];
    const float* enc_w    = (const float*)d_in[4];
    const float* attWa    = (const float*)d_in[5];
    const float* attUa    = (const float*)d_in[6];
    const float* attV     = (const float*)d_in[7];
    const float* W_ih     = (const float*)d_in[8];
    const float* W_hh     = (const float*)d_in[9];
    const float* b_lstm   = (const float*)d_in[10];
    const float* dec_w    = (const float*)d_in[11];
    const float* dec_b    = (const float*)d_in[12];

    float* out      = (float*)d_out;
    float* out_dec  = out;                       // (B, NVOC)
    float* out_ht   = out + (size_t)BB * NVOC;   // (1, B, NH)
    float* out_ct   = out_ht + (size_t)BB * NH;  // (1, B, H2)

    k_init_emb<<<256, 256>>>(inputs, enc_w);
    k_wa<<<dim3(4, 64), 256>>>(h_prev, attWa);
    k_att<<<dim3(NH / BN, MROWS / BM), 256>>>(mem, attUa, attV);
    k_softmax<<<64, 256>>>();
    k_ctx<<<dim3(4, 64), 256>>>(mem);
    k_gates<<<G4 / 64, 256>>>(h_prev, W_ih, W_hh);
    k_lstm<<<(BB * H2) / 256, 256>>>(c_prev, b_lstm, out_ht, out_ct);
    k_dec<<<(NVOC + 127) / 128, 256>>>(dec_w, dec_b, out_ht, out_dec);
}

// round 3
// speedup vs baseline: 1.4741x; 1.4741x over previous
#include <cuda_runtime.h>
#include <cuda_bf16.h>
#include <mma.h>
#include <math.h>

using namespace nvcuda;

#define NVOC 50257
#define NIN  1024
#define NH   1024
#define H2   2048
#define G4   8192
#define BB   64
#define TT   1024
#define MROWS (TT*BB)

// ---------------- scratch ----------------
__device__ float g_wa[BB*NH];
__device__ float g_score[TT*BB];
__device__ float g_ctx[BB*NH];
__device__ float g_emb[BB*NIN];
__device__ float g_gates[BB*G4];

__device__ __forceinline__ float tanh_approx(float x) {
    float y; asm("tanh.approx.f32 %0, %1;" : "=f"(y) : "f"(x)); return y;
}
__device__ __forceinline__ float sigmoid_acc(float x) {
    return 1.0f / (1.0f + expf(-x));
}

// ---------------- 1: zero score + gather embeddings ----------------
__global__ void k_init_emb(const int* __restrict__ inputs,
                           const float* __restrict__ enc_w) {
    int idx = blockIdx.x * blockDim.x + threadIdx.x;
    g_score[idx] = 0.0f;
    int b = idx >> 10, c = idx & 1023;
    g_emb[idx] = enc_w[(size_t)inputs[b] * NIN + c];
}

// ============================================================
// 2: wa = h_prev @ attWa   (64 x 1024, K=1024) — tf32 wmma
// BM=64, BN=128, BK=16, 256 thr, warps 2x4, warp tile 32x32
// ============================================================
__global__ __launch_bounds__(256) void k_wa(const float* __restrict__ h_prev,
                                            const float* __restrict__ attWa) {
    __shared__ float sm[8448];                 // union: stages | Cs
    float* As = sm;                            // [2][64*20]
    float* Bs = sm + 2 * 64 * 20;              // [2][16*136]
    float* Cs = sm;                            // [64][132]

    const int n0  = blockIdx.x * 128;
    const int tid = threadIdx.x;
    const int wid = tid >> 5;
    const int wm  = wid >> 2, wn = wid & 3;

    wmma::fragment<wmma::accumulator, 16, 16, 8, float> acc[2][2];
#pragma unroll
    for (int i = 0; i < 2; i++)
#pragma unroll
        for (int j = 0; j < 2; j++) wmma::fill_fragment(acc[i][j], 0.0f);

    const int am = tid >> 2, aq = tid & 3;           // A: 64x16, 1 float4/thr
    const int br = tid >> 4, bseg = tid & 15;        // B: 16x128, 2 float4/thr

    float4 ra, rb0, rb1;
    auto ldA = [&](int k0) { ra = *(const float4*)(h_prev + am * NH + k0 + aq * 4); };
    auto ldB = [&](int k0) {
        const float* p = attWa + (size_t)(k0 + br) * NH + n0 + bseg * 8;
        rb0 = *(const float4*)p; rb1 = *(const float4*)(p + 4);
    };
    auto stStage = [&](int buf) {
        float* a = As + buf * 64 * 20 + am * 20 + aq * 4;
        a[0]=wmma::__float_to_tf32(ra.x); a[1]=wmma::__float_to_tf32(ra.y);
        a[2]=wmma::__float_to_tf32(ra.z); a[3]=wmma::__float_to_tf32(ra.w);
        float* b = Bs + buf * 16 * 136 + br * 136 + bseg * 8;
        b[0]=wmma::__float_to_tf32(rb0.x); b[1]=wmma::__float_to_tf32(rb0.y);
        b[2]=wmma::__float_to_tf32(rb0.z); b[3]=wmma::__float_to_tf32(rb0.w);
        b[4]=wmma::__float_to_tf32(rb1.x); b[5]=wmma::__float_to_tf32(rb1.y);
        b[6]=wmma::__float_to_tf32(rb1.z); b[7]=wmma::__float_to_tf32(rb1.w);
    };

    ldA(0); ldB(0); stStage(0); __syncthreads();
    const int NIT = NH / 16;
    for (int it = 0; it < NIT; it++) {
        int buf = it & 1;
        if (it < NIT - 1) { ldA((it + 1) * 16); ldB((it + 1) * 16); }
#pragma unroll
        for (int ks = 0; ks < 2; ks++) {
            wmma::fragment<wmma::matrix_a, 16, 16, 8, wmma::precision::tf32, wmma::row_major> af[2];
            wmma::fragment<wmma::matrix_b, 16, 16, 8, wmma::precision::tf32, wmma::row_major> bf[2];
#pragma unroll
            for (int i = 0; i < 2; i++)
                wmma::load_matrix_sync(af[i], As + buf*64*20 + (wm*32 + i*16)*20 + ks*8, 20);
#pragma unroll
            for (int j = 0; j < 2; j++)
                wmma::load_matrix_sync(bf[j], Bs + buf*16*136 + ks*8*136 + wn*32 + j*16, 136);
#pragma unroll
            for (int i = 0; i < 2; i++)
#pragma unroll
                for (int j = 0; j < 2; j++) wmma::mma_sync(acc[i][j], af[i], bf[j], acc[i][j]);
        }
        if (it < NIT - 1) stStage(buf ^ 1);
        __syncthreads();
    }
#pragma unroll
    for (int i = 0; i < 2; i++)
#pragma unroll
        for (int j = 0; j < 2; j++)
            wmma::store_matrix_sync(Cs + (wm*32 + i*16)*132 + wn*32 + j*16,
                                    acc[i][j], 132, wmma::mem_row_major);
    __syncthreads();
    {
        int b = tid >> 2, seg = tid & 3;
#pragma unroll
        for (int k = 0; k < 32; k++)
            g_wa[b * NH + n0 + seg * 32 + k] = Cs[b * 132 + seg * 32 + k];
    }
}

// ============================================================
// 3: fused attention GEMM (bf16 wmma)
// score[row] += sum_j attV[j]*tanh((mem@attUa)[row,j] + wa[b,j])
// BM=256, BN=128, BK=16, 256 thr, warps 4x2, warp tile 64x64
// ============================================================
#define ALD 24
#define BLD 136

__global__ __launch_bounds__(256, 1) void k_att(const float* __restrict__ mem,
                                                const float* __restrict__ attUa,
                                                const float* __restrict__ attV) {
    __shared__ __align__(16) __nv_bfloat16 sA[2][256 * ALD];   // 24576 B
    __shared__ __align__(16) __nv_bfloat16 sB[2][16 * BLD];    //  8704 B

    const int row0 = blockIdx.y * 256;
    const int n0   = blockIdx.x * 128;
    const int tid  = threadIdx.x;
    const int wid  = tid >> 5;
    const int lane = tid & 31;
    const int wm   = wid >> 1;   // 0..3 (64 rows)
    const int wn   = wid & 1;    // 0..1 (64 cols)

    wmma::fragment<wmma::accumulator, 16, 16, 16, float> acc[4][4];
#pragma unroll
    for (int i = 0; i < 4; i++)
#pragma unroll
        for (int j = 0; j < 4; j++) wmma::fill_fragment(acc[i][j], 0.0f);

    const int brow = tid >> 4, bseg = tid & 15;   // B: 16x128, 8 elems/thr

    __nv_bfloat162 hA[8], hB[4];
    auto ldA = [&](int k0) {
        const float4* p = (const float4*)(mem + (size_t)(row0 + tid) * NH + k0);
#pragma unroll
        for (int i = 0; i < 4; i++) {
            float4 v = p[i];
            hA[2*i]   = __float22bfloat162_rn(make_float2(v.x, v.y));
            hA[2*i+1] = __float22bfloat162_rn(make_float2(v.z, v.w));
        }
    };
    auto ldB = [&](int k0) {
        const float4* p = (const float4*)(attUa + (size_t)(k0 + brow) * NH + n0 + bseg * 8);
#pragma unroll
        for (int i = 0; i < 2; i++) {
            float4 v = p[i];
            hB[2*i]   = __float22bfloat162_rn(make_float2(v.x, v.y));
            hB[2*i+1] = __float22bfloat162_rn(make_float2(v.z, v.w));
        }
    };
    auto stStage = [&](int buf) {
        uint4* da = (uint4*)&sA[buf][tid * ALD];
        da[0] = *(uint4*)&hA[0];
        da[1] = *(uint4*)&hA[4];
        *(uint4*)&sB[buf][brow * BLD + bseg * 8] = *(uint4*)&hB[0];
    };

    ldA(0); ldB(0); stStage(0); __syncthreads();
    for (int it = 0; it < 64; it++) {
        int buf = it & 1;
        if (it < 63) { ldA((it + 1) * 16); ldB((it + 1) * 16); }
        {
            wmma::fragment<wmma::matrix_a, 16, 16, 16, __nv_bfloat16, wmma::row_major> af[4];
            wmma::fragment<wmma::matrix_b, 16, 16, 16, __nv_bfloat16, wmma::row_major> bf[4];
#pragma unroll
            for (int i = 0; i < 4; i++)
                wmma::load_matrix_sync(af[i], &sA[buf][(wm*64 + i*16) * ALD], ALD);
#pragma unroll
            for (int j = 0; j < 4; j++)
                wmma::load_matrix_sync(bf[j], &sB[buf][wn*64 + j*16], BLD);
#pragma unroll
            for (int i = 0; i < 4; i++)
#pragma unroll
                for (int j = 0; j < 4; j++) wmma::mma_sync(acc[i][j], af[i], bf[j], acc[i][j]);
        }
        if (it < 63) stStage(buf ^ 1);
        __syncthreads();
    }

    // epilogue: per-warp scratch (reuse sA), 16x32 chunks
    float* scr = ((float*)&sA[0][0]) + wid * (16 * 36);
    const int r = lane >> 1, half = lane & 1;
#pragma unroll
    for (int i = 0; i < 4; i++) {
        float p = 0.0f;
        int row = row0 + wm * 64 + i * 16 + r;
        int b = row & (BB - 1);
#pragma unroll
        for (int jh = 0; jh < 2; jh++) {
            wmma::store_matrix_sync(scr,      acc[i][jh*2],   36, wmma::mem_row_major);
            wmma::store_matrix_sync(scr + 16, acc[i][jh*2+1], 36, wmma::mem_row_major);
            __syncwarp();
            int colbase = n0 + wn * 64 + jh * 32 + half * 16;
            const float* crow = scr + r * 36 + half * 16;
            const float* wap  = g_wa + b * NH + colbase;
            const float* avp  = attV + colbase;
#pragma unroll
            for (int jj = 0; jj < 16; jj++)
                p += __ldg(avp + jj) * tanh_approx(crow[jj] + __ldg(wap + jj));
            __syncwarp();
        }
        p += __shfl_down_sync(0xffffffffu, p, 1);
        if (half == 0) atomicAdd(&g_score[row], p);
    }
}

// ---------------- 4: softmax over t ----------------
__global__ void k_softmax() {
    int b = blockIdx.x;
    int tid = threadIdx.x;
    __shared__ float red[256];
    float vals[4];
    float mx = -1e30f;
#pragma unroll
    for (int i = 0; i < 4; i++) {
        vals[i] = g_score[(tid + i * 256) * BB + b];
        mx = fmaxf(mx, vals[i]);
    }
    red[tid] = mx; __syncthreads();
    for (int s = 128; s > 0; s >>= 1) {
        if (tid < s) red[tid] = fmaxf(red[tid], red[tid + s]);
        __syncthreads();
    }
    mx = red[0]; __syncthreads();
    float sum = 0.0f;
#pragma unroll
    for (int i = 0; i < 4; i++) { vals[i] = expf(vals[i] - mx); sum += vals[i]; }
    red[tid] = sum; __syncthreads();
    for (int s = 128; s > 0; s >>= 1) {
        if (tid < s) red[tid] += red[tid + s];
        __syncthreads();
    }
    float inv = 1.0f / red[0];
#pragma unroll
    for (int i = 0; i < 4; i++)
        g_score[(tid + i * 256) * BB + b] = vals[i] * inv;
}

// ---------------- 5: context ----------------
__global__ void k_ctx(const float* __restrict__ mem) {
    int b = blockIdx.y;
    int j = blockIdx.x * 256 + threadIdx.x;
    __shared__ float w[TT];
    for (int t = threadIdx.x; t < TT; t += 256) w[t] = g_score[t * BB + b];
    __syncthreads();
    float acc = 0.0f;
#pragma unroll 4
    for (int t = 0; t < TT; t++)
        acc += w[t] * mem[((size_t)t * BB + b) * NH + j];
    g_ctx[b * NH + j] = acc;
}

// ============================================================
// 6: gates = [emb|h|ctx] @ [W_ih;W_hh]  (64 x 8192, K=3072) — tf32
// BM=64, BN=128, BK=16, 256 thr, warps 2x4, warp 32x32
// ============================================================
__global__ __launch_bounds__(256) void k_gates(const float* __restrict__ h_prev,
                                               const float* __restrict__ W_ih,
                                               const float* __restrict__ W_hh) {
    __shared__ float sm[8448];
    float* As = sm;
    float* Bs = sm + 2 * 64 * 20;
    float* Cs = sm;

    const int n0  = blockIdx.x * 128;
    const int tid = threadIdx.x;
    const int wid = tid >> 5;
    const int wm  = wid >> 2, wn = wid & 3;

    wmma::fragment<wmma::accumulator, 16, 16, 8, float> acc[2][2];
#pragma unroll
    for (int i = 0; i < 2; i++)
#pragma unroll
        for (int j = 0; j < 2; j++) wmma::fill_fragment(acc[i][j], 0.0f);

    const int am = tid >> 2, aq = tid & 3;
    const int br = tid >> 4, bseg = tid & 15;

    float4 ra, rb0, rb1;
    auto ldA = [&](int k0) {
        const float* src;
        if (k0 < 1024)      src = g_emb + am * 1024 + k0;
        else if (k0 < 2048) src = h_prev + am * 1024 + (k0 - 1024);
        else                src = g_ctx + am * 1024 + (k0 - 2048);
        ra = *(const float4*)(src + aq * 4);
    };
    auto ldB = [&](int k0) {
        int krow = k0 + br;
        const float* wsrc = (krow < 1024) ? (W_ih + (size_t)krow * G4)
                                          : (W_hh + (size_t)(krow - 1024) * G4);
        const float* p = wsrc + n0 + bseg * 8;
        rb0 = *(const float4*)p; rb1 = *(const float4*)(p + 4);
    };
    auto stStage = [&](int buf) {
        float* a = As + buf * 64 * 20 + am * 20 + aq * 4;
        a[0]=wmma::__float_to_tf32(ra.x); a[1]=wmma::__float_to_tf32(ra.y);
        a[2]=wmma::__float_to_tf32(ra.z); a[3]=wmma::__float_to_tf32(ra.w);
        float* b = Bs + buf * 16 * 136 + br * 136 + bseg * 8;
        b[0]=wmma::__float_to_tf32(rb0.x); b[1]=wmma::__float_to_tf32(rb0.y);
        b[2]=wmma::__float_to_tf32(rb0.z); b[3]=wmma::__float_to_tf32(rb0.w);
        b[4]=wmma::__float_to_tf32(rb1.x); b[5]=wmma::__float_to_tf32(rb1.y);
        b[6]=wmma::__float_to_tf32(rb1.z); b[7]=wmma::__float_to_tf32(rb1.w);
    };

    ldA(0); ldB(0); stStage(0); __syncthreads();
    const int NIT = 3072 / 16;
    for (int it = 0; it < NIT; it++) {
        int buf = it & 1;
        if (it < NIT - 1) { ldA((it + 1) * 16); ldB((it + 1) * 16); }
#pragma unroll
        for (int ks = 0; ks < 2; ks++) {
            wmma::fragment<wmma::matrix_a, 16, 16, 8, wmma::precision::tf32, wmma::row_major> af[2];
            wmma::fragment<wmma::matrix_b, 16, 16, 8, wmma::precision::tf32, wmma::row_major> bf[2];
#pragma unroll
            for (int i = 0; i < 2; i++)
                wmma::load_matrix_sync(af[i], As + buf*64*20 + (wm*32 + i*16)*20 + ks*8, 20);
#pragma unroll
            for (int j = 0; j < 2; j++)
                wmma::load_matrix_sync(bf[j], Bs + buf*16*136 + ks*8*136 + wn*32 + j*16, 136);
#pragma unroll
            for (int i = 0; i < 2; i++)
#pragma unroll
                for (int j = 0; j < 2; j++) wmma::mma_sync(acc[i][j], af[i], bf[j], acc[i][j]);
        }
        if (it < NIT - 1) stStage(buf ^ 1);
        __syncthreads();
    }
#pragma unroll
    for (int i = 0; i < 2; i++)
#pragma unroll
        for (int j = 0; j < 2; j++)
            wmma::store_matrix_sync(Cs + (wm*32 + i*16)*132 + wn*32 + j*16,
                                    acc[i][j], 132, wmma::mem_row_major);
    __syncthreads();
    {
        int b = tid >> 2, seg = tid & 3;
#pragma unroll
        for (int k = 0; k < 32; k++)
            g_gates[(size_t)b * G4 + n0 + seg * 32 + k] = Cs[b * 132 + seg * 32 + k];
    }
}

// ---------------- 7: LSTM elementwise ----------------
__global__ void k_lstm(const float* __restrict__ c_prev,
                       const float* __restrict__ b_lstm,
                       float* __restrict__ out_ht,
                       float* __restrict__ out_ct) {
    int idx = blockIdx.x * 256 + threadIdx.x;
    int b = idx >> 11, n = idx & 2047;
    const float* g = g_gates + (size_t)b * G4;
    float i_ = g[n]        + b_lstm[n];
    float f_ = g[n + 2048] + b_lstm[n + 2048];
    float gg = g[n + 4096] + b_lstm[n + 4096];
    float o_ = g[n + 6144] + b_lstm[n + 6144];
    float c = sigmoid_acc(f_) * c_prev[idx] + sigmoid_acc(i_) * tanhf(gg);
    out_ct[idx] = c;
    float h = sigmoid_acc(o_) * tanhf(c);
    if (n < 1024) out_ht[b * 1024 + n] = h;
}

// ============================================================
// 8: decoded = ht @ dec_w^T + dec_b  (50257 x 64, K=1024) — tf32
// BM=128(v), BN=64(b), BK=16, 256 thr, warps 4x2, warp 32x32
// ============================================================
__global__ __launch_bounds__(256) void k_dec(const float* __restrict__ dec_w,
                                             const float* __restrict__ dec_b,
                                             const float* __restrict__ ht,
                                             float* __restrict__ out) {
    __shared__ float sm[8448];                 // union: stages | CsT
    float* As  = sm;                           // [2][128*20]
    float* Bs  = sm + 2 * 128 * 20;            // [2][64*20]
    float* CsT = sm;                           // [64 b][132] (b-major, v contiguous)

    const int v0  = blockIdx.x * 128;
    const int tid = threadIdx.x;
    const int wid = tid >> 5;
    const int wm  = wid >> 1, wn = wid & 1;

    wmma::fragment<wmma::accumulator, 16, 16, 8, float> acc[2][2];
#pragma unroll
    for (int i = 0; i < 2; i++)
#pragma unroll
        for (int j = 0; j < 2; j++) wmma::fill_fragment(acc[i][j], 0.0f);

    const int ar = tid >> 1, ah = tid & 1;     // A: 128x16, 8 fp32/thr
    const int bb = tid >> 2, bq = tid & 3;     // B: 64x16, 4 fp32/thr

    float4 ra0, ra1, rb;
    auto ldA = [&](int k0) {
        if (v0 + ar < NVOC) {
            const float* p = dec_w + (size_t)(v0 + ar) * 1024 + k0 + ah * 8;
            ra0 = *(const float4*)p; ra1 = *(const float4*)(p + 4);
        } else {
            ra0 = make_float4(0,0,0,0); ra1 = ra0;
        }
    };
    auto ldB = [&](int k0) { rb = *(const float4*)(ht + bb * 1024 + k0 + bq * 4); };
    auto stStage = [&](int buf) {
        float* a = As + buf * 128 * 20 + ar * 20 + ah * 8;
        a[0]=wmma::__float_to_tf32(ra0.x); a[1]=wmma::__float_to_tf32(ra0.y);
        a[2]=wmma::__float_to_tf32(ra0.z); a[3]=wmma::__float_to_tf32(ra0.w);
        a[4]=wmma::__float_to_tf32(ra1.x); a[5]=wmma::__float_to_tf32(ra1.y);
        a[6]=wmma::__float_to_tf32(ra1.z); a[7]=wmma::__float_to_tf32(ra1.w);
        float* b = Bs + buf * 64 * 20 + bb * 20 + bq * 4;
        b[0]=wmma::__float_to_tf32(rb.x); b[1]=wmma::__float_to_tf32(rb.y);
        b[2]=wmma::__float_to_tf32(rb.z); b[3]=wmma::__float_to_tf32(rb.w);
    };

    ldA(0); ldB(0); stStage(0); __syncthreads();
    for (int it = 0; it < 64; it++) {
        int buf = it & 1;
        if (it < 63) { ldA((it + 1) * 16); ldB((it + 1) * 16); }
#pragma unroll
        for (int ks = 0; ks < 2; ks++) {
            wmma::fragment<wmma::matrix_a, 16, 16, 8, wmma::precision::tf32, wmma::row_major> af[2];
            wmma::fragment<wmma::matrix_b, 16, 16, 8, wmma::precision::tf32, wmma::col_major> bf[2];
#pragma unroll
            for (int i = 0; i < 2; i++)
                wmma::load_matrix_sync(af[i], As + buf*128*20 + (wm*32 + i*16)*20 + ks*8, 20);
#pragma unroll
            for (int j = 0; j < 2; j++)
                wmma::load_matrix_sync(bf[j], Bs + buf*64*20 + (wn*32 + j*16)*20 + ks*8, 20);
#pragma unroll
            for (int i = 0; i < 2; i++)
#pragma unroll
                for (int j = 0; j < 2; j++) wmma::mma_sync(acc[i][j], af[i], bf[j], acc[i][j]);
        }
        if (it < 63) stStage(buf ^ 1);
        __syncthreads();
    }
    // transposed store: CsT[b][v] — col_major store of (v,b) tiles
#pragma unroll
    for (int i = 0; i < 2; i++)
#pragma unroll
        for (int j = 0; j < 2; j++)
            wmma::store_matrix_sync(CsT + (wn*32 + j*16)*132 + wm*32 + i*16,
                                    acc[i][j], 132, wmma::mem_col_major);
    __syncthreads();
    {
        int b = tid >> 2, seg = tid & 3;
#pragma unroll
        for (int k = 0; k < 32; k++) {
            int v = v0 + seg * 32 + k;
            if (v < NVOC)
                out[(size_t)b * NVOC + v] = CsT[b * 132 + seg * 32 + k] + __ldg(dec_b + v);
        }
    }
}

// ---------------- launch ----------------
extern "C" void kernel_launch(void* const* d_in, const int* in_sizes, int n_in,
                              void* d_out, int out_size) {
    const int*   inputs   = (const int*)  d_in[0];
    const float* mem      = (const float*)d_in[1];
    const float* h_prev   = (const float*)d_in[2];
    const float* c_prev   = (const float*)d_in[3];
    const float* enc_w    = (const float*)d_in[4];
    const float* attWa    = (const float*)d_in[5];
    const float* attUa    = (const float*)d_in[6];
    const float* attV     = (const float*)d_in[7];
    const float* W_ih     = (const float*)d_in[8];
    const float* W_hh     = (const float*)d_in[9];
    const float* b_lstm   = (const float*)d_in[10];
    const float* dec_w    = (const float*)d_in[11];
    const float* dec_b    = (const float*)d_in[12];

    float* out      = (float*)d_out;
    float* out_dec  = out;
    float* out_ht   = out + (size_t)BB * NVOC;
    float* out_ct   = out_ht + (size_t)BB * NH;

    k_init_emb<<<256, 256>>>(inputs, enc_w);
    k_wa<<<8, 256>>>(h_prev, attWa);
    k_att<<<dim3(8, 256), 256>>>(mem, attUa, attV);
    k_softmax<<<64, 256>>>();
    k_ctx<<<dim3(4, 64), 256>>>(mem);
    k_gates<<<64, 256>>>(h_prev, W_ih, W_hh);
    k_lstm<<<(BB * H2) / 256, 256>>>(c_prev, b_lstm, out_ht, out_ct);
    k_dec<<<(NVOC + 127) / 128, 256>>>(dec_w, dec_b, out_ht, out_dec);
}

// round 4
// speedup vs baseline: 1.5896x; 1.0784x over previous
#include <cuda_runtime.h>
#include <cuda_bf16.h>
#include <mma.h>
#include <math.h>

using namespace nvcuda;

#define NVOC 50257
#define NIN  1024
#define NH   1024
#define H2   2048
#define G4   8192
#define BB   64
#define TT   1024
#define MROWS (TT*BB)

// ---------------- scratch ----------------
__device__ float g_wa[BB*NH];
__device__ float g_score[TT*BB];
__device__ float g_ctx[BB*NH];
__device__ float g_emb[BB*NIN];
__device__ float g_gp[3][BB*G4];   // split-K gate partials

__device__ __forceinline__ float tanh_approx(float x) {
    float y; asm("tanh.approx.f32 %0, %1;" : "=f"(y) : "f"(x)); return y;
}
__device__ __forceinline__ float sigmoid_acc(float x) {
    return 1.0f / (1.0f + expf(-x));
}

// ---------------- 1: zero score + gather embeddings ----------------
__global__ void k_init_emb(const int* __restrict__ inputs,
                           const float* __restrict__ enc_w) {
    int idx = blockIdx.x * blockDim.x + threadIdx.x;
    g_score[idx] = 0.0f;
    int b = idx >> 10, c = idx & 1023;
    g_emb[idx] = enc_w[(size_t)inputs[b] * NIN + c];
}

// ============================================================
// 2: wa = h_prev @ attWa   (64 x 1024, K=1024) — tf32 wmma
// ============================================================
__global__ __launch_bounds__(256) void k_wa(const float* __restrict__ h_prev,
                                            const float* __restrict__ attWa) {
    __shared__ float sm[8448];
    float* As = sm;                            // [2][64*20]
    float* Bs = sm + 2 * 64 * 20;              // [2][16*136]
    float* Cs = sm;                            // [64][132]

    const int n0  = blockIdx.x * 128;
    const int tid = threadIdx.x;
    const int wid = tid >> 5;
    const int wm  = wid >> 2, wn = wid & 3;

    wmma::fragment<wmma::accumulator, 16, 16, 8, float> acc[2][2];
#pragma unroll
    for (int i = 0; i < 2; i++)
#pragma unroll
        for (int j = 0; j < 2; j++) wmma::fill_fragment(acc[i][j], 0.0f);

    const int am = tid >> 2, aq = tid & 3;
    const int br = tid >> 4, bseg = tid & 15;

    float4 ra, rb0, rb1;
    auto ldA = [&](int k0) { ra = *(const float4*)(h_prev + am * NH + k0 + aq * 4); };
    auto ldB = [&](int k0) {
        const float* p = attWa + (size_t)(k0 + br) * NH + n0 + bseg * 8;
        rb0 = *(const float4*)p; rb1 = *(const float4*)(p + 4);
    };
    auto stStage = [&](int buf) {
        float* a = As + buf * 64 * 20 + am * 20 + aq * 4;
        a[0]=wmma::__float_to_tf32(ra.x); a[1]=wmma::__float_to_tf32(ra.y);
        a[2]=wmma::__float_to_tf32(ra.z); a[3]=wmma::__float_to_tf32(ra.w);
        float* b = Bs + buf * 16 * 136 + br * 136 + bseg * 8;
        b[0]=wmma::__float_to_tf32(rb0.x); b[1]=wmma::__float_to_tf32(rb0.y);
        b[2]=wmma::__float_to_tf32(rb0.z); b[3]=wmma::__float_to_tf32(rb0.w);
        b[4]=wmma::__float_to_tf32(rb1.x); b[5]=wmma::__float_to_tf32(rb1.y);
        b[6]=wmma::__float_to_tf32(rb1.z); b[7]=wmma::__float_to_tf32(rb1.w);
    };

    ldA(0); ldB(0); stStage(0); __syncthreads();
    const int NIT = NH / 16;
    for (int it = 0; it < NIT; it++) {
        int buf = it & 1;
        if (it < NIT - 1) { ldA((it + 1) * 16); ldB((it + 1) * 16); }
#pragma unroll
        for (int ks = 0; ks < 2; ks++) {
            wmma::fragment<wmma::matrix_a, 16, 16, 8, wmma::precision::tf32, wmma::row_major> af[2];
            wmma::fragment<wmma::matrix_b, 16, 16, 8, wmma::precision::tf32, wmma::row_major> bf[2];
#pragma unroll
            for (int i = 0; i < 2; i++)
                wmma::load_matrix_sync(af[i], As + buf*64*20 + (wm*32 + i*16)*20 + ks*8, 20);
#pragma unroll
            for (int j = 0; j < 2; j++)
                wmma::load_matrix_sync(bf[j], Bs + buf*16*136 + ks*8*136 + wn*32 + j*16, 136);
#pragma unroll
            for (int i = 0; i < 2; i++)
#pragma unroll
                for (int j = 0; j < 2; j++) wmma::mma_sync(acc[i][j], af[i], bf[j], acc[i][j]);
        }
        if (it < NIT - 1) stStage(buf ^ 1);
        __syncthreads();
    }
#pragma unroll
    for (int i = 0; i < 2; i++)
#pragma unroll
        for (int j = 0; j < 2; j++)
            wmma::store_matrix_sync(Cs + (wm*32 + i*16)*132 + wn*32 + j*16,
                                    acc[i][j], 132, wmma::mem_row_major);
    __syncthreads();
    {
        int b = tid >> 2, seg = tid & 3;
#pragma unroll
        for (int k = 0; k < 32; k++)
            g_wa[b * NH + n0 + seg * 32 + k] = Cs[b * 132 + seg * 32 + k];
    }
}

// ============================================================
// 3: fused attention GEMM (bf16 wmma) — no-spill config
// BM=128, BN=128, BK=32, 256 thr, warps 4x2, warp tile 32x64
// ============================================================
#define ALD 40    // bf16 elems per A smem row (32 + 8 pad)
#define BLD 136   // bf16 elems per B smem row (128 + 8 pad)
#define A_STAGE (128*ALD)   // 5120 bf16
#define B_STAGE (32*BLD)    // 4352 bf16

__global__ __launch_bounds__(256) void k_att(const float* __restrict__ mem,
                                             const float* __restrict__ attUa,
                                             const float* __restrict__ attV) {
    __shared__ __align__(16) char smem_raw[2*A_STAGE*2 + 2*B_STAGE*2]; // 37888 B
    __nv_bfloat16* sA = (__nv_bfloat16*)smem_raw;
    __nv_bfloat16* sB = (__nv_bfloat16*)(smem_raw + 2*A_STAGE*2);

    const int row0 = blockIdx.y * 128;
    const int n0   = blockIdx.x * 128;
    const int tid  = threadIdx.x;
    const int wid  = tid >> 5;
    const int lane = tid & 31;
    const int wm   = wid >> 1;   // 0..3 : 32-row strip
    const int wn   = wid & 1;    // 0..1 : 64-col strip

    wmma::fragment<wmma::accumulator, 16, 16, 16, float> acc[2][4];
#pragma unroll
    for (int i = 0; i < 2; i++)
#pragma unroll
        for (int j = 0; j < 4; j++) wmma::fill_fragment(acc[i][j], 0.0f);

    const int arow = tid >> 1, ahalf = tid & 1;   // A: 128x32, 16 elems/thr
    const int brow = tid >> 3, bseg = tid & 7;    // B: 32x128, 16 elems/thr

    __nv_bfloat162 hA[8], hB[8];
    auto ldA = [&](int k0) {
        const float4* p = (const float4*)(mem + (size_t)(row0 + arow) * NH + k0 + ahalf * 16);
#pragma unroll
        for (int i = 0; i < 4; i++) {
            float4 v = p[i];
            hA[2*i]   = __float22bfloat162_rn(make_float2(v.x, v.y));
            hA[2*i+1] = __float22bfloat162_rn(make_float2(v.z, v.w));
        }
    };
    auto ldB = [&](int k0) {
        const float4* p = (const float4*)(attUa + (size_t)(k0 + brow) * NH + n0 + bseg * 16);
#pragma unroll
        for (int i = 0; i < 4; i++) {
            float4 v = p[i];
            hB[2*i]   = __float22bfloat162_rn(make_float2(v.x, v.y));
            hB[2*i+1] = __float22bfloat162_rn(make_float2(v.z, v.w));
        }
    };
    auto stStage = [&](int buf) {
        uint4* da = (uint4*)&sA[buf*A_STAGE + arow*ALD + ahalf*16];
        da[0] = *(uint4*)&hA[0]; da[1] = *(uint4*)&hA[4];
        uint4* db = (uint4*)&sB[buf*B_STAGE + brow*BLD + bseg*16];
        db[0] = *(uint4*)&hB[0]; db[1] = *(uint4*)&hB[4];
    };

    ldA(0); ldB(0); stStage(0); __syncthreads();
    const int NIT = NH / 32;   // 32
    for (int it = 0; it < NIT; it++) {
        int buf = it & 1;
        if (it < NIT - 1) { ldA((it + 1) * 32); ldB((it + 1) * 32); }
#pragma unroll
        for (int ks = 0; ks < 2; ks++) {
            wmma::fragment<wmma::matrix_a, 16, 16, 16, __nv_bfloat16, wmma::row_major> af[2];
            wmma::fragment<wmma::matrix_b, 16, 16, 16, __nv_bfloat16, wmma::row_major> bf[4];
#pragma unroll
            for (int i = 0; i < 2; i++)
                wmma::load_matrix_sync(af[i], &sA[buf*A_STAGE + (wm*32 + i*16)*ALD + ks*16], ALD);
#pragma unroll
            for (int j = 0; j < 4; j++)
                wmma::load_matrix_sync(bf[j], &sB[buf*B_STAGE + ks*16*BLD + wn*64 + j*16], BLD);
#pragma unroll
            for (int i = 0; i < 2; i++)
#pragma unroll
                for (int j = 0; j < 4; j++) wmma::mma_sync(acc[i][j], af[i], bf[j], acc[i][j]);
        }
        if (it < NIT - 1) stStage(buf ^ 1);
        __syncthreads();
    }

    // epilogue: per-warp scratch 16x68 floats (reuse pipeline smem)
    float* scr = (float*)smem_raw + wid * (16 * 68);
    const int r = lane >> 1, half = lane & 1;
#pragma unroll
    for (int i = 0; i < 2; i++) {
        float p = 0.0f;
        int row = row0 + wm * 32 + i * 16 + r;
        int b = row & (BB - 1);
#pragma unroll
        for (int j = 0; j < 4; j++)
            wmma::store_matrix_sync(scr + j * 16, acc[i][j], 68, wmma::mem_row_major);
        __syncwarp();
        int colbase = n0 + wn * 64 + half * 32;
        const float* crow = scr + r * 68 + half * 32;
        const float* wap  = g_wa + b * NH + colbase;
        const float* avp  = attV + colbase;
#pragma unroll
        for (int jj = 0; jj < 32; jj++)
            p += __ldg(avp + jj) * tanh_approx(crow[jj] + __ldg(wap + jj));
        __syncwarp();
        p += __shfl_down_sync(0xffffffffu, p, 1);
        if (half == 0) atomicAdd(&g_score[row], p);
    }
}

// ---------------- 4: softmax over t ----------------
__global__ void k_softmax() {
    int b = blockIdx.x;
    int tid = threadIdx.x;
    __shared__ float red[256];
    float vals[4];
    float mx = -1e30f;
#pragma unroll
    for (int i = 0; i < 4; i++) {
        vals[i] = g_score[(tid + i * 256) * BB + b];
        mx = fmaxf(mx, vals[i]);
    }
    red[tid] = mx; __syncthreads();
    for (int s = 128; s > 0; s >>= 1) {
        if (tid < s) red[tid] = fmaxf(red[tid], red[tid + s]);
        __syncthreads();
    }
    mx = red[0]; __syncthreads();
    float sum = 0.0f;
#pragma unroll
    for (int i = 0; i < 4; i++) { vals[i] = expf(vals[i] - mx); sum += vals[i]; }
    red[tid] = sum; __syncthreads();
    for (int s = 128; s > 0; s >>= 1) {
        if (tid < s) red[tid] += red[tid + s];
        __syncthreads();
    }
    float inv = 1.0f / red[0];
#pragma unroll
    for (int i = 0; i < 4; i++)
        g_score[(tid + i * 256) * BB + b] = vals[i] * inv;
}

// ---------------- 5: context ----------------
__global__ void k_ctx(const float* __restrict__ mem) {
    int b = blockIdx.y;
    int j = blockIdx.x * 256 + threadIdx.x;
    __shared__ float w[TT];
    for (int t = threadIdx.x; t < TT; t += 256) w[t] = g_score[t * BB + b];
    __syncthreads();
    float acc = 0.0f;
#pragma unroll 4
    for (int t = 0; t < TT; t++)
        acc += w[t] * mem[((size_t)t * BB + b) * NH + j];
    g_ctx[b * NH + j] = acc;
}

// ============================================================
// 6: gates split-K: part p of [emb|h|ctx] @ W  (64 x 8192, K=1024 each)
// grid (64, 3); tf32 wmma, BM=64, BN=128, BK=16
// ============================================================
__global__ __launch_bounds__(256) void k_gates(const float* __restrict__ h_prev,
                                               const float* __restrict__ W_ih,
                                               const float* __restrict__ W_hh) {
    __shared__ float sm[8448];
    float* As = sm;
    float* Bs = sm + 2 * 64 * 20;
    float* Cs = sm;

    const int n0   = blockIdx.x * 128;
    const int part = blockIdx.y;
    const int tid  = threadIdx.x;
    const int wid  = tid >> 5;
    const int wm   = wid >> 2, wn = wid & 3;

    const float* Asrc = (part == 0) ? g_emb : (part == 1) ? h_prev : g_ctx;
    const float* Bsrc = (part == 0) ? W_ih  : (W_hh + (part == 2 ? (size_t)1024 * G4 : 0));
    float* outp = g_gp[part];

    wmma::fragment<wmma::accumulator, 16, 16, 8, float> acc[2][2];
#pragma unroll
    for (int i = 0; i < 2; i++)
#pragma unroll
        for (int j = 0; j < 2; j++) wmma::fill_fragment(acc[i][j], 0.0f);

    const int am = tid >> 2, aq = tid & 3;
    const int br = tid >> 4, bseg = tid & 15;

    float4 ra, rb0, rb1;
    auto ldA = [&](int k0) { ra = *(const float4*)(Asrc + am * 1024 + k0 + aq * 4); };
    auto ldB = [&](int k0) {
        const float* p = Bsrc + (size_t)(k0 + br) * G4 + n0 + bseg * 8;
        rb0 = *(const float4*)p; rb1 = *(const float4*)(p + 4);
    };
    auto stStage = [&](int buf) {
        float* a = As + buf * 64 * 20 + am * 20 + aq * 4;
        a[0]=wmma::__float_to_tf32(ra.x); a[1]=wmma::__float_to_tf32(ra.y);
        a[2]=wmma::__float_to_tf32(ra.z); a[3]=wmma::__float_to_tf32(ra.w);
        float* b = Bs + buf * 16 * 136 + br * 136 + bseg * 8;
        b[0]=wmma::__float_to_tf32(rb0.x); b[1]=wmma::__float_to_tf32(rb0.y);
        b[2]=wmma::__float_to_tf32(rb0.z); b[3]=wmma::__float_to_tf32(rb0.w);
        b[4]=wmma::__float_to_tf32(rb1.x); b[5]=wmma::__float_to_tf32(rb1.y);
        b[6]=wmma::__float_to_tf32(rb1.z); b[7]=wmma::__float_to_tf32(rb1.w);
    };

    ldA(0); ldB(0); stStage(0); __syncthreads();
    const int NIT = 1024 / 16;
    for (int it = 0; it < NIT; it++) {
        int buf = it & 1;
        if (it < NIT - 1) { ldA((it + 1) * 16); ldB((it + 1) * 16); }
#pragma unroll
        for (int ks = 0; ks < 2; ks++) {
            wmma::fragment<wmma::matrix_a, 16, 16, 8, wmma::precision::tf32, wmma::row_major> af[2];
            wmma::fragment<wmma::matrix_b, 16, 16, 8, wmma::precision::tf32, wmma::row_major> bf[2];
#pragma unroll
            for (int i = 0; i < 2; i++)
                wmma::load_matrix_sync(af[i], As + buf*64*20 + (wm*32 + i*16)*20 + ks*8, 20);
#pragma unroll
            for (int j = 0; j < 2; j++)
                wmma::load_matrix_sync(bf[j], Bs + buf*16*136 + ks*8*136 + wn*32 + j*16, 136);
#pragma unroll
            for (int i = 0; i < 2; i++)
#pragma unroll
                for (int j = 0; j < 2; j++) wmma::mma_sync(acc[i][j], af[i], bf[j], acc[i][j]);
        }
        if (it < NIT - 1) stStage(buf ^ 1);
        __syncthreads();
    }
#pragma unroll
    for (int i = 0; i < 2; i++)
#pragma unroll
        for (int j = 0; j < 2; j++)
            wmma::store_matrix_sync(Cs + (wm*32 + i*16)*132 + wn*32 + j*16,
                                    acc[i][j], 132, wmma::mem_row_major);
    __syncthreads();
    {
        int b = tid >> 2, seg = tid & 3;
#pragma unroll
        for (int k = 0; k < 32; k++)
            outp[(size_t)b * G4 + n0 + seg * 32 + k] = Cs[b * 132 + seg * 32 + k];
    }
}

// ---------------- 7: LSTM elementwise (sums 3 gate partials) ----------------
__global__ void k_lstm(const float* __restrict__ c_prev,
                       const float* __restrict__ b_lstm,
                       float* __restrict__ out_ht,
                       float* __restrict__ out_ct) {
    int idx = blockIdx.x * 256 + threadIdx.x;
    int b = idx >> 11, n = idx & 2047;
    const float* g0 = g_gp[0] + (size_t)b * G4;
    const float* g1 = g_gp[1] + (size_t)b * G4;
    const float* g2 = g_gp[2] + (size_t)b * G4;
    float i_ = g0[n]        + g1[n]        + g2[n]        + b_lstm[n];
    float f_ = g0[n + 2048] + g1[n + 2048] + g2[n + 2048] + b_lstm[n + 2048];
    float gg = g0[n + 4096] + g1[n + 4096] + g2[n + 4096] + b_lstm[n + 4096];
    float o_ = g0[n + 6144] + g1[n + 6144] + g2[n + 6144] + b_lstm[n + 6144];
    float c = sigmoid_acc(f_) * c_prev[idx] + sigmoid_acc(i_) * tanhf(gg);
    out_ct[idx] = c;
    float h = sigmoid_acc(o_) * tanhf(c);
    if (n < 1024) out_ht[b * 1024 + n] = h;
}

// ============================================================
// 8: decoded = ht @ dec_w^T + dec_b  (50257 x 64, K=1024) — tf32
// ============================================================
__global__ __launch_bounds__(256) void k_dec(const float* __restrict__ dec_w,
                                             const float* __restrict__ dec_b,
                                             const float* __restrict__ ht,
                                             float* __restrict__ out) {
    __shared__ float sm[8448];
    float* As  = sm;                           // [2][128*20]
    float* Bs  = sm + 2 * 128 * 20;            // [2][64*20]
    float* CsT = sm;                           // [64][132]

    const int v0  = blockIdx.x * 128;
    const int tid = threadIdx.x;
    const int wid = tid >> 5;
    const int wm  = wid >> 1, wn = wid & 1;

    wmma::fragment<wmma::accumulator, 16, 16, 8, float> acc[2][2];
#pragma unroll
    for (int i = 0; i < 2; i++)
#pragma unroll
        for (int j = 0; j < 2; j++) wmma::fill_fragment(acc[i][j], 0.0f);

    const int ar = tid >> 1, ah = tid & 1;
    const int bb = tid >> 2, bq = tid & 3;

    float4 ra0, ra1, rb;
    auto ldA = [&](int k0) {
        if (v0 + ar < NVOC) {
            const float* p = dec_w + (size_t)(v0 + ar) * 1024 + k0 + ah * 8;
            ra0 = *(const float4*)p; ra1 = *(const float4*)(p + 4);
        } else {
            ra0 = make_float4(0,0,0,0); ra1 = ra0;
        }
    };
    auto ldB = [&](int k0) { rb = *(const float4*)(ht + bb * 1024 + k0 + bq * 4); };
    auto stStage = [&](int buf) {
        float* a = As + buf * 128 * 20 + ar * 20 + ah * 8;
        a[0]=wmma::__float_to_tf32(ra0.x); a[1]=wmma::__float_to_tf32(ra0.y);
        a[2]=wmma::__float_to_tf32(ra0.z); a[3]=wmma::__float_to_tf32(ra0.w);
        a[4]=wmma::__float_to_tf32(ra1.x); a[5]=wmma::__float_to_tf32(ra1.y);
        a[6]=wmma::__float_to_tf32(ra1.z); a[7]=wmma::__float_to_tf32(ra1.w);
        float* b = Bs + buf * 64 * 20 + bb * 20 + bq * 4;
        b[0]=wmma::__float_to_tf32(rb.x); b[1]=wmma::__float_to_tf32(rb.y);
        b[2]=wmma::__float_to_tf32(rb.z); b[3]=wmma::__float_to_tf32(rb.w);
    };

    ldA(0); ldB(0); stStage(0); __syncthreads();
    for (int it = 0; it < 64; it++) {
        int buf = it & 1;
        if (it < 63) { ldA((it + 1) * 16); ldB((it + 1) * 16); }
#pragma unroll
        for (int ks = 0; ks < 2; ks++) {
            wmma::fragment<wmma::matrix_a, 16, 16, 8, wmma::precision::tf32, wmma::row_major> af[2];
            wmma::fragment<wmma::matrix_b, 16, 16, 8, wmma::precision::tf32, wmma::col_major> bf[2];
#pragma unroll
            for (int i = 0; i < 2; i++)
                wmma::load_matrix_sync(af[i], As + buf*128*20 + (wm*32 + i*16)*20 + ks*8, 20);
#pragma unroll
            for (int j = 0; j < 2; j++)
                wmma::load_matrix_sync(bf[j], Bs + buf*64*20 + (wn*32 + j*16)*20 + ks*8, 20);
#pragma unroll
            for (int i = 0; i < 2; i++)
#pragma unroll
                for (int j = 0; j < 2; j++) wmma::mma_sync(acc[i][j], af[i], bf[j], acc[i][j]);
        }
        if (it < 63) stStage(buf ^ 1);
        __syncthreads();
    }
#pragma unroll
    for (int i = 0; i < 2; i++)
#pragma unroll
        for (int j = 0; j < 2; j++)
            wmma::store_matrix_sync(CsT + (wn*32 + j*16)*132 + wm*32 + i*16,
                                    acc[i][j], 132, wmma::mem_col_major);
    __syncthreads();
    {
        int b = tid >> 2, seg = tid & 3;
#pragma unroll
        for (int k = 0; k < 32; k++) {
            int v = v0 + seg * 32 + k;
            if (v < NVOC)
                out[(size_t)b * NVOC + v] = CsT[b * 132 + seg * 32 + k] + __ldg(dec_b + v);
        }
    }
}

// ---------------- launch ----------------
extern "C" void kernel_launch(void* const* d_in, const int* in_sizes, int n_in,
                              void* d_out, int out_size) {
    const int*   inputs   = (const int*)  d_in[0];
    const float* mem      = (const float*)d_in[1];
    const float* h_prev   = (const float*)d_in[2];
    const float* c_prev   = (const float*)d_in[3];
    const float* enc_w    = (const float*)d_in[4];
    const float* attWa    = (const float*)d_in[5];
    const float* attUa    = (const float*)d_in[6];
    const float* attV     = (const float*)d_in[7];
    const float* W_ih     = (const float*)d_in[8];
    const float* W_hh     = (const float*)d_in[9];
    const float* b_lstm   = (const float*)d_in[10];
    const float* dec_w    = (const float*)d_in[11];
    const float* dec_b    = (const float*)d_in[12];

    float* out      = (float*)d_out;
    float* out_dec  = out;
    float* out_ht   = out + (size_t)BB * NVOC;
    float* out_ct   = out_ht + (size_t)BB * NH;

    k_init_emb<<<256, 256>>>(inputs, enc_w);
    k_wa<<<8, 256>>>(h_prev, attWa);
    k_att<<<dim3(8, 512), 256>>>(mem, attUa, attV);
    k_softmax<<<64, 256>>>();
    k_ctx<<<dim3(4, 64), 256>>>(mem);
    k_gates<<<dim3(64, 3), 256>>>(h_prev, W_ih, W_hh);
    k_lstm<<<(BB * H2) / 256, 256>>>(c_prev, b_lstm, out_ht, out_ct);
    k_dec<<<(NVOC + 127) / 128, 256>>>(dec_w, dec_b, out_ht, out_dec);
}

// round 6
// speedup vs baseline: 2.1763x; 1.3691x over previous
#include <cuda_runtime.h>
#include <cuda_bf16.h>
#include <mma.h>
#include <math.h>

using namespace nvcuda;

#define NVOC 50257
#define NIN  1024
#define NH   1024
#define H2   2048
#define G4   8192
#define BB   64
#define TT   1024
#define MROWS (TT*BB)

// ---------------- scratch ----------------
__device__ float g_wa[BB*NH];
__device__ float g_score[TT*BB];
__device__ float g_ctx[BB*NH];
__device__ float g_emb[BB*NIN];
__device__ float g_gp[3][BB*G4];
__device__ __nv_bfloat16 g_Uh[NH*NH];   // attUa in bf16

__device__ __forceinline__ float tanh_approx(float x) {
    float y; asm("tanh.approx.f32 %0, %1;" : "=f"(y) : "f"(x)); return y;
}
__device__ __forceinline__ float sigmoid_acc(float x) {
    return 1.0f / (1.0f + expf(-x));
}

// ---------------- 1: zero score + gather embeddings ----------------
__global__ void k_init_emb(const int* __restrict__ inputs,
                           const float* __restrict__ enc_w) {
    int idx = blockIdx.x * blockDim.x + threadIdx.x;
    g_score[idx] = 0.0f;
    int b = idx >> 10, c = idx & 1023;
    g_emb[idx] = enc_w[(size_t)inputs[b] * NIN + c];
}

// ---------------- 1b: convert attUa -> bf16 ----------------
__global__ void k_cvtU(const float* __restrict__ attUa) {
    int idx = blockIdx.x * blockDim.x + threadIdx.x;   // float4 index, 262144
    float4 v = *(const float4*)(attUa + (size_t)idx * 4);
    __nv_bfloat162 h0 = __float22bfloat162_rn(make_float2(v.x, v.y));
    __nv_bfloat162 h1 = __float22bfloat162_rn(make_float2(v.z, v.w));
    uint2 u; u.x = *(unsigned*)&h0; u.y = *(unsigned*)&h1;
    *(uint2*)&g_Uh[(size_t)idx * 4] = u;
}

// ============================================================
// 2: wa = h_prev @ attWa   (64 x 1024, K=1024) — tf32 wmma
// ============================================================
__global__ __launch_bounds__(256) void k_wa(const float* __restrict__ h_prev,
                                            const float* __restrict__ attWa) {
    __shared__ float sm[8448];
    float* As = sm;
    float* Bs = sm + 2 * 64 * 20;
    float* Cs = sm;

    const int n0  = blockIdx.x * 128;
    const int tid = threadIdx.x;
    const int wid = tid >> 5;
    const int wm  = wid >> 2, wn = wid & 3;

    wmma::fragment<wmma::accumulator, 16, 16, 8, float> acc[2][2];
#pragma unroll
    for (int i = 0; i < 2; i++)
#pragma unroll
        for (int j = 0; j < 2; j++) wmma::fill_fragment(acc[i][j], 0.0f);

    const int am = tid >> 2, aq = tid & 3;
    const int br = tid >> 4, bseg = tid & 15;

    float4 ra, rb0, rb1;
    auto ldA = [&](int k0) { ra = *(const float4*)(h_prev + am * NH + k0 + aq * 4); };
    auto ldB = [&](int k0) {
        const float* p = attWa + (size_t)(k0 + br) * NH + n0 + bseg * 8;
        rb0 = *(const float4*)p; rb1 = *(const float4*)(p + 4);
    };
    auto stStage = [&](int buf) {
        float* a = As + buf * 64 * 20 + am * 20 + aq * 4;
        a[0]=wmma::__float_to_tf32(ra.x); a[1]=wmma::__float_to_tf32(ra.y);
        a[2]=wmma::__float_to_tf32(ra.z); a[3]=wmma::__float_to_tf32(ra.w);
        float* b = Bs + buf * 16 * 136 + br * 136 + bseg * 8;
        b[0]=wmma::__float_to_tf32(rb0.x); b[1]=wmma::__float_to_tf32(rb0.y);
        b[2]=wmma::__float_to_tf32(rb0.z); b[3]=wmma::__float_to_tf32(rb0.w);
        b[4]=wmma::__float_to_tf32(rb1.x); b[5]=wmma::__float_to_tf32(rb1.y);
        b[6]=wmma::__float_to_tf32(rb1.z); b[7]=wmma::__float_to_tf32(rb1.w);
    };

    ldA(0); ldB(0); stStage(0); __syncthreads();
    const int NIT = NH / 16;
    for (int it = 0; it < NIT; it++) {
        int buf = it & 1;
        if (it < NIT - 1) { ldA((it + 1) * 16); ldB((it + 1) * 16); }
#pragma unroll
        for (int ks = 0; ks < 2; ks++) {
            wmma::fragment<wmma::matrix_a, 16, 16, 8, wmma::precision::tf32, wmma::row_major> af[2];
            wmma::fragment<wmma::matrix_b, 16, 16, 8, wmma::precision::tf32, wmma::row_major> bf[2];
#pragma unroll
            for (int i = 0; i < 2; i++)
                wmma::load_matrix_sync(af[i], As + buf*64*20 + (wm*32 + i*16)*20 + ks*8, 20);
#pragma unroll
            for (int j = 0; j < 2; j++)
                wmma::load_matrix_sync(bf[j], Bs + buf*16*136 + ks*8*136 + wn*32 + j*16, 136);
#pragma unroll
            for (int i = 0; i < 2; i++)
#pragma unroll
                for (int j = 0; j < 2; j++) wmma::mma_sync(acc[i][j], af[i], bf[j], acc[i][j]);
        }
        if (it < NIT - 1) stStage(buf ^ 1);
        __syncthreads();
    }
#pragma unroll
    for (int i = 0; i < 2; i++)
#pragma unroll
        for (int j = 0; j < 2; j++)
            wmma::store_matrix_sync(Cs + (wm*32 + i*16)*132 + wn*32 + j*16,
                                    acc[i][j], 132, wmma::mem_row_major);
    __syncthreads();
    {
        int b = tid >> 2, seg = tid & 3;
#pragma unroll
        for (int k = 0; k < 32; k++)
            g_wa[b * NH + n0 + seg * 32 + k] = Cs[b * 132 + seg * 32 + k];
    }
}

// ============================================================
// 3: fused attention GEMM — A-resident design
// One CTA per timestep t: A = mem[t] (64x1024) resident in smem (bf16).
// Loops n0 over 4 chunks of 256 cols of attUa (bf16 global, L2-resident).
// Warp grid 2x4, warp tile 32x64. Score accumulated in registers.
// ============================================================
#define AT_LDA 1032             // A smem row stride (bf16 elems)
#define AT_BLD 264              // B smem row stride (bf16 elems)
#define AT_SA_BYTES (64 * AT_LDA * 2)          // 132096
#define AT_SB_BYTES (2 * 32 * AT_BLD * 2)      // 33792
#define AT_SC_BYTES (8 * 16 * 68 * 4)          // 34816
#define AT_SMEM (AT_SA_BYTES + AT_SB_BYTES + AT_SC_BYTES)  // 200704

__global__ __launch_bounds__(256) void k_att(const float* __restrict__ mem,
                                             const float* __restrict__ attV) {
    extern __shared__ __align__(16) char dyn[];
    __nv_bfloat16* sA = (__nv_bfloat16*)dyn;
    __nv_bfloat16* sB = (__nv_bfloat16*)(dyn + AT_SA_BYTES);
    float* scratch   = (float*)(dyn + AT_SA_BYTES + AT_SB_BYTES);

    const int row0 = blockIdx.x * 64;          // = t*64
    const int tid  = threadIdx.x;
    const int wid  = tid >> 5;
    const int lane = tid & 31;
    const int wm   = wid >> 2;                 // 0..1  (32-row strip)
    const int wn   = wid & 3;                  // 0..3  (64-col strip)

    // ---- load A panel once: 64x1024 fp32 -> bf16 smem ----
#pragma unroll 8
    for (int i = 0; i < 64; i++) {
        int idx = tid + i * 256;               // float4 index within 64x256
        int r = idx >> 8, c4 = idx & 255;
        float4 v = *(const float4*)(mem + (size_t)(row0 + r) * NH + c4 * 4);
        __nv_bfloat162 h0 = __float22bfloat162_rn(make_float2(v.x, v.y));
        __nv_bfloat162 h1 = __float22bfloat162_rn(make_float2(v.z, v.w));
        uint2 u; u.x = *(unsigned*)&h0; u.y = *(unsigned*)&h1;
        *(uint2*)&sA[r * AT_LDA + c4 * 4] = u;
    }
    __syncthreads();

    float pAcc[2] = {0.0f, 0.0f};
    const int r    = lane >> 1;
    const int half = lane & 1;

    uint4 rB[4];
    auto ldB = [&](int n0, int kt) {
        const __nv_bfloat16* base = g_Uh + (size_t)(kt * 32) * NH + n0 * 256;
#pragma unroll
        for (int i = 0; i < 4; i++) {
            int idx = tid + i * 256;           // uint4 index within 32x32
            int rr = idx >> 5, cc = idx & 31;
            rB[i] = *(const uint4*)(base + (size_t)rr * NH + cc * 8);
        }
    };
    auto stB = [&](int buf) {
#pragma unroll
        for (int i = 0; i < 4; i++) {
            int idx = tid + i * 256;
            int rr = idx >> 5, cc = idx & 31;
            *(uint4*)&sB[buf * 32 * AT_BLD + rr * AT_BLD + cc * 8] = rB[i];
        }
    };

    for (int n0 = 0; n0 < 4; n0++) {
        wmma::fragment<wmma::accumulator, 16, 16, 16, float> acc[2][4];
#pragma unroll
        for (int i = 0; i < 2; i++)
#pragma unroll
            for (int j = 0; j < 4; j++) wmma::fill_fragment(acc[i][j], 0.0f);

        ldB(n0, 0); stB(0); __syncthreads();
        for (int kt = 0; kt < 32; kt++) {
            int buf = kt & 1;
            if (kt < 31) ldB(n0, kt + 1);
#pragma unroll
            for (int ks = 0; ks < 2; ks++) {
                wmma::fragment<wmma::matrix_a, 16, 16, 16, __nv_bfloat16, wmma::row_major> af[2];
                wmma::fragment<wmma::matrix_b, 16, 16, 16, __nv_bfloat16, wmma::row_major> bf[4];
#pragma unroll
                for (int i = 0; i < 2; i++)
                    wmma::load_matrix_sync(af[i], &sA[(wm*32 + i*16) * AT_LDA + kt*32 + ks*16], AT_LDA);
#pragma unroll
                for (int j = 0; j < 4; j++)
                    wmma::load_matrix_sync(bf[j], &sB[buf*32*AT_BLD + ks*16*AT_BLD + wn*64 + j*16], AT_BLD);
#pragma unroll
                for (int i = 0; i < 2; i++)
#pragma unroll
                    for (int j = 0; j < 4; j++) wmma::mma_sync(acc[i][j], af[i], bf[j], acc[i][j]);
            }
            if (kt < 31) stB(buf ^ 1);
            __syncthreads();
        }

        // epilogue for this n0 chunk: tanh + attV dot, accumulate in regs
        float* sc = scratch + wid * (16 * 68);
#pragma unroll
        for (int i = 0; i < 2; i++) {
#pragma unroll
            for (int j = 0; j < 4; j++)
                wmma::store_matrix_sync(sc + j * 16, acc[i][j], 68, wmma::mem_row_major);
            __syncwarp();
            int b = wm * 32 + i * 16 + r;
            int colbase = n0 * 256 + wn * 64 + half * 32;
            const float* crow = sc + r * 68 + half * 32;
            const float* wap  = g_wa + b * NH + colbase;
            const float* avp  = attV + colbase;
            float p = 0.0f;
#pragma unroll
            for (int q = 0; q < 8; q++) {
                float4 av = *(const float4*)(avp + q * 4);
                float4 wa = *(const float4*)(wap + q * 4);
                p += av.x * tanh_approx(crow[q*4+0] + wa.x);
                p += av.y * tanh_approx(crow[q*4+1] + wa.y);
                p += av.z * tanh_approx(crow[q*4+2] + wa.z);
                p += av.w * tanh_approx(crow[q*4+3] + wa.w);
            }
            __syncwarp();
            p += __shfl_down_sync(0xffffffffu, p, 1);
            if (half == 0) pAcc[i] += p;
        }
        __syncthreads();
    }

    if (half == 0) {
#pragma unroll
        for (int i = 0; i < 2; i++)
            atomicAdd(&g_score[row0 + wm * 32 + i * 16 + r], pAcc[i]);
    }
}

// ---------------- 4: softmax over t ----------------
__global__ void k_softmax() {
    int b = blockIdx.x;
    int tid = threadIdx.x;
    __shared__ float red[256];
    float vals[4];
    float mx = -1e30f;
#pragma unroll
    for (int i = 0; i < 4; i++) {
        vals[i] = g_score[(tid + i * 256) * BB + b];
        mx = fmaxf(mx, vals[i]);
    }
    red[tid] = mx; __syncthreads();
    for (int s = 128; s > 0; s >>= 1) {
        if (tid < s) red[tid] = fmaxf(red[tid], red[tid + s]);
        __syncthreads();
    }
    mx = red[0]; __syncthreads();
    float sum = 0.0f;
#pragma unroll
    for (int i = 0; i < 4; i++) { vals[i] = expf(vals[i] - mx); sum += vals[i]; }
    red[tid] = sum; __syncthreads();
    for (int s = 128; s > 0; s >>= 1) {
        if (tid < s) red[tid] += red[tid + s];
        __syncthreads();
    }
    float inv = 1.0f / red[0];
#pragma unroll
    for (int i = 0; i < 4; i++)
        g_score[(tid + i * 256) * BB + b] = vals[i] * inv;
}

// ---------------- 5: context ----------------
__global__ void k_ctx(const float* __restrict__ mem) {
    int b = blockIdx.y;
    int j = blockIdx.x * 256 + threadIdx.x;
    __shared__ float w[TT];
    for (int t = threadIdx.x; t < TT; t += 256) w[t] = g_score[t * BB + b];
    __syncthreads();
    float acc = 0.0f;
#pragma unroll 4
    for (int t = 0; t < TT; t++)
        acc += w[t] * mem[((size_t)t * BB + b) * NH + j];
    g_ctx[b * NH + j] = acc;
}

// ============================================================
// 6: gates split-K (grid 64 x 3) — tf32 wmma
// ============================================================
__global__ __launch_bounds__(256) void k_gates(const float* __restrict__ h_prev,
                                               const float* __restrict__ W_ih,
                                               const float* __restrict__ W_hh) {
    __shared__ float sm[8448];
    float* As = sm;
    float* Bs = sm + 2 * 64 * 20;
    float* Cs = sm;

    const int n0   = blockIdx.x * 128;
    const int part = blockIdx.y;
    const int tid  = threadIdx.x;
    const int wid  = tid >> 5;
    const int wm   = wid >> 2, wn = wid & 3;

    const float* Asrc = (part == 0) ? g_emb : (part == 1) ? h_prev : g_ctx;
    const float* Bsrc = (part == 0) ? W_ih  : (W_hh + (part == 2 ? (size_t)1024 * G4 : 0));
    float* outp = g_gp[part];

    wmma::fragment<wmma::accumulator, 16, 16, 8, float> acc[2][2];
#pragma unroll
    for (int i = 0; i < 2; i++)
#pragma unroll
        for (int j = 0; j < 2; j++) wmma::fill_fragment(acc[i][j], 0.0f);

    const int am = tid >> 2, aq = tid & 3;
    const int br = tid >> 4, bseg = tid & 15;

    float4 ra, rb0, rb1;
    auto ldA = [&](int k0) { ra = *(const float4*)(Asrc + am * 1024 + k0 + aq * 4); };
    auto ldB = [&](int k0) {
        const float* p = Bsrc + (size_t)(k0 + br) * G4 + n0 + bseg * 8;
        rb0 = *(const float4*)p; rb1 = *(const float4*)(p + 4);
    };
    auto stStage = [&](int buf) {
        float* a = As + buf * 64 * 20 + am * 20 + aq * 4;
        a[0]=wmma::__float_to_tf32(ra.x); a[1]=wmma::__float_to_tf32(ra.y);
        a[2]=wmma::__float_to_tf32(ra.z); a[3]=wmma::__float_to_tf32(ra.w);
        float* b = Bs + buf * 16 * 136 + br * 136 + bseg * 8;
        b[0]=wmma::__float_to_tf32(rb0.x); b[1]=wmma::__float_to_tf32(rb0.y);
        b[2]=wmma::__float_to_tf32(rb0.z); b[3]=wmma::__float_to_tf32(rb0.w);
        b[4]=wmma::__float_to_tf32(rb1.x); b[5]=wmma::__float_to_tf32(rb1.y);
        b[6]=wmma::__float_to_tf32(rb1.z); b[7]=wmma::__float_to_tf32(rb1.w);
    };

    ldA(0); ldB(0); stStage(0); __syncthreads();
    const int NIT = 1024 / 16;
    for (int it = 0; it < NIT; it++) {
        int buf = it & 1;
        if (it < NIT - 1) { ldA((it + 1) * 16); ldB((it + 1) * 16); }
#pragma unroll
        for (int ks = 0; ks < 2; ks++) {
            wmma::fragment<wmma::matrix_a, 16, 16, 8, wmma::precision::tf32, wmma::row_major> af[2];
            wmma::fragment<wmma::matrix_b, 16, 16, 8, wmma::precision::tf32, wmma::row_major> bf[2];
#pragma unroll
            for (int i = 0; i < 2; i++)
                wmma::load_matrix_sync(af[i], As + buf*64*20 + (wm*32 + i*16)*20 + ks*8, 20);
#pragma unroll
            for (int j = 0; j < 2; j++)
                wmma::load_matrix_sync(bf[j], Bs + buf*16*136 + ks*8*136 + wn*32 + j*16, 136);
#pragma unroll
            for (int i = 0; i < 2; i++)
#pragma unroll
                for (int j = 0; j < 2; j++) wmma::mma_sync(acc[i][j], af[i], bf[j], acc[i][j]);
        }
        if (it < NIT - 1) stStage(buf ^ 1);
        __syncthreads();
    }
#pragma unroll
    for (int i = 0; i < 2; i++)
#pragma unroll
        for (int j = 0; j < 2; j++)
            wmma::store_matrix_sync(Cs + (wm*32 + i*16)*132 + wn*32 + j*16,
                                    acc[i][j], 132, wmma::mem_row_major);
    __syncthreads();
    {
        int b = tid >> 2, seg = tid & 3;
#pragma unroll
        for (int k = 0; k < 32; k++)
            outp[(size_t)b * G4 + n0 + seg * 32 + k] = Cs[b * 132 + seg * 32 + k];
    }
}

// ---------------- 7: LSTM elementwise ----------------
__global__ void k_lstm(const float* __restrict__ c_prev,
                       const float* __restrict__ b_lstm,
                       float* __restrict__ out_ht,
                       float* __restrict__ out_ct) {
    int idx = blockIdx.x * 256 + threadIdx.x;
    int b = idx >> 11, n = idx & 2047;
    const float* g0 = g_gp[0] + (size_t)b * G4;
    const float* g1 = g_gp[1] + (size_t)b * G4;
    const float* g2 = g_gp[2] + (size_t)b * G4;
    float i_ = g0[n]        + g1[n]        + g2[n]        + b_lstm[n];
    float f_ = g0[n + 2048] + g1[n + 2048] + g2[n + 2048] + b_lstm[n + 2048];
    float gg = g0[n + 4096] + g1[n + 4096] + g2[n + 4096] + b_lstm[n + 4096];
    float o_ = g0[n + 6144] + g1[n + 6144] + g2[n + 6144] + b_lstm[n + 6144];
    float c = sigmoid_acc(f_) * c_prev[idx] + sigmoid_acc(i_) * tanhf(gg);
    out_ct[idx] = c;
    float h = sigmoid_acc(o_) * tanhf(c);
    if (n < 1024) out_ht[b * 1024 + n] = h;
}

// ============================================================
// 8: decoded = ht @ dec_w^T + dec_b — tf32 wmma
// ============================================================
__global__ __launch_bounds__(256) void k_dec(const float* __restrict__ dec_w,
                                             const float* __restrict__ dec_b,
                                             const float* __restrict__ ht,
                                             float* __restrict__ out) {
    __shared__ float sm[8448];
    float* As  = sm;
    float* Bs  = sm + 2 * 128 * 20;
    float* CsT = sm;

    const int v0  = blockIdx.x * 128;
    const int tid = threadIdx.x;
    const int wid = tid >> 5;
    const int wm  = wid >> 1, wn = wid & 1;

    wmma::fragment<wmma::accumulator, 16, 16, 8, float> acc[2][2];
#pragma unroll
    for (int i = 0; i < 2; i++)
#pragma unroll
        for (int j = 0; j < 2; j++) wmma::fill_fragment(acc[i][j], 0.0f);

    const int ar = tid >> 1, ah = tid & 1;
    const int bb = tid >> 2, bq = tid & 3;

    float4 ra0, ra1, rb;
    auto ldA = [&](int k0) {
        if (v0 + ar < NVOC) {
            const float* p = dec_w + (size_t)(v0 + ar) * 1024 + k0 + ah * 8;
            ra0 = *(const float4*)p; ra1 = *(const float4*)(p + 4);
        } else {
            ra0 = make_float4(0,0,0,0); ra1 = ra0;
        }
    };
    auto ldB = [&](int k0) { rb = *(const float4*)(ht + bb * 1024 + k0 + bq * 4); };
    auto stStage = [&](int buf) {
        float* a = As + buf * 128 * 20 + ar * 20 + ah * 8;
        a[0]=wmma::__float_to_tf32(ra0.x); a[1]=wmma::__float_to_tf32(ra0.y);
        a[2]=wmma::__float_to_tf32(ra0.z); a[3]=wmma::__float_to_tf32(ra0.w);
        a[4]=wmma::__float_to_tf32(ra1.x); a[5]=wmma::__float_to_tf32(ra1.y);
        a[6]=wmma::__float_to_tf32(ra1.z); a[7]=wmma::__float_to_tf32(ra1.w);
        float* b = Bs + buf * 64 * 20 + bb * 20 + bq * 4;
        b[0]=wmma::__float_to_tf32(rb.x); b[1]=wmma::__float_to_tf32(rb.y);
        b[2]=wmma::__float_to_tf32(rb.z); b[3]=wmma::__float_to_tf32(rb.w);
    };

    ldA(0); ldB(0); stStage(0); __syncthreads();
    for (int it = 0; it < 64; it++) {
        int buf = it & 1;
        if (it < 63) { ldA((it + 1) * 16); ldB((it + 1) * 16); }
#pragma unroll
        for (int ks = 0; ks < 2; ks++) {
            wmma::fragment<wmma::matrix_a, 16, 16, 8, wmma::precision::tf32, wmma::row_major> af[2];
            wmma::fragment<wmma::matrix_b, 16, 16, 8, wmma::precision::tf32, wmma::col_major> bf[2];
#pragma unroll
            for (int i = 0; i < 2; i++)
                wmma::load_matrix_sync(af[i], As + buf*128*20 + (wm*32 + i*16)*20 + ks*8, 20);
#pragma unroll
            for (int j = 0; j < 2; j++)
                wmma::load_matrix_sync(bf[j], Bs + buf*64*20 + (wn*32 + j*16)*20 + ks*8, 20);
#pragma unroll
            for (int i = 0; i < 2; i++)
#pragma unroll
                for (int j = 0; j < 2; j++) wmma::mma_sync(acc[i][j], af[i], bf[j], acc[i][j]);
        }
        if (it < 63) stStage(buf ^ 1);
        __syncthreads();
    }
#pragma unroll
    for (int i = 0; i < 2; i++)
#pragma unroll
        for (int j = 0; j < 2; j++)
            wmma::store_matrix_sync(CsT + (wn*32 + j*16)*132 + wm*32 + i*16,
                                    acc[i][j], 132, wmma::mem_col_major);
    __syncthreads();
    {
        int b = tid >> 2, seg = tid & 3;
#pragma unroll
        for (int k = 0; k < 32; k++) {
            int v = v0 + seg * 32 + k;
            if (v < NVOC)
                out[(size_t)b * NVOC + v] = CsT[b * 132 + seg * 32 + k] + __ldg(dec_b + v);
        }
    }
}

// ---------------- launch ----------------
extern "C" void kernel_launch(void* const* d_in, const int* in_sizes, int n_in,
                              void* d_out, int out_size) {
    const int*   inputs   = (const int*)  d_in[0];
    const float* mem      = (const float*)d_in[1];
    const float* h_prev   = (const float*)d_in[2];
    const float* c_prev   = (const float*)d_in[3];
    const float* enc_w    = (const float*)d_in[4];
    const float* attWa    = (const float*)d_in[5];
    const float* attUa    = (const float*)d_in[6];
    const float* attV     = (const float*)d_in[7];
    const float* W_ih     = (const float*)d_in[8];
    const float* W_hh     = (const float*)d_in[9];
    const float* b_lstm   = (const float*)d_in[10];
    const float* dec_w    = (const float*)d_in[11];
    const float* dec_b    = (const float*)d_in[12];

    float* out      = (float*)d_out;
    float* out_dec  = out;
    float* out_ht   = out + (size_t)BB * NVOC;
    float* out_ct   = out_ht + (size_t)BB * NH;

    static bool attr_set = false;
    if (!attr_set) {
        cudaFuncSetAttribute(k_att, cudaFuncAttributeMaxDynamicSharedMemorySize, AT_SMEM);
        attr_set = true;
    }

    k_init_emb<<<256, 256>>>(inputs, enc_w);
    k_cvtU<<<1024, 256>>>(attUa);
    k_wa<<<8, 256>>>(h_prev, attWa);
    k_att<<<1024, 256, AT_SMEM>>>(mem, attV);
    k_softmax<<<64, 256>>>();
    k_ctx<<<dim3(4, 64), 256>>>(mem);
    k_gates<<<dim3(64, 3), 256>>>(h_prev, W_ih, W_hh);
    k_lstm<<<(BB * H2) / 256, 256>>>(c_prev, b_lstm, out_ht, out_ct);
    k_dec<<<(NVOC + 127) / 128, 256>>>(dec_w, dec_b, out_ht, out_dec);
}